// round 6
// baseline (speedup 1.0000x reference)
#include <cuda_runtime.h>
#include <cuda_bf16.h>
#include <math.h>

// ---------------------------------------------------------------------------
// Problem constants
// ---------------------------------------------------------------------------
#define BATCH  8192
#define IN_D   512
#define CTX_D  256
#define CENTER 512
#define FF_D   1024
#define RNN_D  1024
#define OUT_D  512
#define O2C_D  256
#define TOT_D  768

typedef unsigned long long ull;

// ---------------------------------------------------------------------------
// Scratch (no cudaMalloc allowed -> __device__ globals)
// ---------------------------------------------------------------------------
__device__ float g_partials[256];
__device__ float g_scale;
__device__ float g_Wcomb[CENTER * FF_D];         // 512 x 1024 (2 MB)
__device__ float g_rnn_in[(size_t)BATCH * FF_D]; // 8192 x 1024 (32 MB)

// ---------------------------------------------------------------------------
// Packed fp32x2 helpers (sm_100+ PTX)
// ---------------------------------------------------------------------------
#define FMA2(accv, av, bv) \
    asm("fma.rn.f32x2 %0, %1, %2, %0;" : "+l"(accv) : "l"(av), "l"(bv))

#define PACK2(outv, x) \
    asm("mov.b64 %0, {%1, %2};" : "=l"(outv) \
        : "r"(__float_as_uint(x)), "r"(__float_as_uint(x)))

#define UNPACK2(lo, hi, p) do { \
    unsigned _lo, _hi; \
    asm("mov.b64 {%0, %1}, %2;" : "=r"(_lo), "=r"(_hi) : "l"(p)); \
    (lo) = __uint_as_float(_lo); (hi) = __uint_as_float(_hi); \
} while (0)

// ---------------------------------------------------------------------------
// Norm of W_read -> g_scale = 1 / max(||W_read||_F, 1)
// ---------------------------------------------------------------------------
__global__ void norm_partial_kernel(const float* __restrict__ W) {
    __shared__ float sh[256];
    const int n = CENTER * CTX_D; // 131072
    float s = 0.0f;
    for (int i = blockIdx.x * 256 + threadIdx.x; i < n; i += 256 * 256) {
        float v = W[i];
        s += v * v;
    }
    sh[threadIdx.x] = s;
    __syncthreads();
    for (int off = 128; off > 0; off >>= 1) {
        if (threadIdx.x < off) sh[threadIdx.x] += sh[threadIdx.x + off];
        __syncthreads();
    }
    if (threadIdx.x == 0) g_partials[blockIdx.x] = sh[0];
}

__global__ void norm_finish_kernel() {
    __shared__ float sh[256];
    sh[threadIdx.x] = g_partials[threadIdx.x];
    __syncthreads();
    for (int off = 128; off > 0; off >>= 1) {
        if (threadIdx.x < off) sh[threadIdx.x] += sh[threadIdx.x + off];
        __syncthreads();
    }
    if (threadIdx.x == 0) g_scale = 1.0f / fmaxf(sqrtf(sh[0]), 1.0f);
}

// ---------------------------------------------------------------------------
// Generic dual-segment 128x128x8 tiled GEMM with fused epilogue.
//   C = epilogue( [A0 | A1] @ [B0 ; B1] )
// A segments row-major (M x K), B segments row-major (K x N).
// K0 = rows in segment 0; K0 and Ktot multiples of 8; M, N multiples of 128.
//
// MODE 0: C0 = acc * g_scale                      (weight precombine)
// MODE 1: C0 = relu(acc + bias)                   (pre layer)
// MODE 2: C0 = tanh(acc + bias)                   (rnn cell)
// MODE 3: split relu(acc + bias): cols [0,512) -> C0 (ld 512),
//         cols [512,768) -> C1 (ld 256)           (post layer)
// ---------------------------------------------------------------------------
template <int MODE>
__global__ void __launch_bounds__(256, 2) gemm128_kernel(
    const float* __restrict__ A0, int lda0, int K0,
    const float* __restrict__ A1, int lda1,
    const float* __restrict__ B0, int ldb0,
    const float* __restrict__ B1, int ldb1,
    int Ktot,
    const float* __restrict__ bias,
    float* __restrict__ C0, int ldc0,
    float* __restrict__ C1)
{
    __shared__ float As[8][128]; // [k][m]
    __shared__ float Bs[8][128]; // [k][n]

    const int tid = threadIdx.x;
    const int tx  = tid & 15;   // 16 col groups
    const int ty  = tid >> 4;   // 16 row groups
    const int bm  = blockIdx.y * 128;
    const int bn  = blockIdx.x * 128;

    // A tile load mapping: 128 rows x 8 k, float4 per thread
    const int aRow = tid >> 1;         // 0..127
    const int aK   = (tid & 1) * 4;    // 0 or 4
    // B tile load mapping: 8 rows x 128 cols, float4 per thread
    const int bRow = tid >> 5;         // 0..7
    const int bCol = (tid & 31) * 4;   // 0..124

    // Accumulators: 8 rows x 4 col-pairs (8 cols), packed f32x2 along cols.
    ull acc[8][4];
#pragma unroll
    for (int r = 0; r < 8; r++)
#pragma unroll
        for (int j = 0; j < 4; j++) acc[r][j] = 0ull;

    // Two clean segment loops: uniform base addresses, no per-iter select.
#pragma unroll 1
    for (int seg = 0; seg < 2; seg++) {
        const float* __restrict__ Ap = seg ? A1 : A0;
        const float* __restrict__ Bp = seg ? B1 : B0;
        const int lda  = seg ? lda1 : lda0;
        const int ldb  = seg ? ldb1 : ldb0;
        const int klen = seg ? (Ktot - K0) : K0;
        if (klen <= 0) continue;

        const float* aPtr = Ap + (size_t)(bm + aRow) * lda + aK;
        const float* bPtr = Bp + (size_t)bRow * ldb + (bn + bCol);

#pragma unroll 1
        for (int k0 = 0; k0 < klen; k0 += 8) {
            float4 av = *(const float4*)(aPtr + k0);
            float4 bv = *(const float4*)(bPtr + (size_t)k0 * ldb);

            __syncthreads(); // previous iteration's compute done before overwrite
            As[aK + 0][aRow] = av.x;
            As[aK + 1][aRow] = av.y;
            As[aK + 2][aRow] = av.z;
            As[aK + 3][aRow] = av.w;
            *(float4*)&Bs[bRow][bCol] = bv;
            __syncthreads();

#pragma unroll
            for (int kk = 0; kk < 8; kk++) {
                float4 alo = *(const float4*)&As[kk][ty * 4];
                float4 ahi = *(const float4*)&As[kk][64 + ty * 4];
                ulonglong2 blo = *(const ulonglong2*)&Bs[kk][tx * 4];
                ulonglong2 bhi = *(const ulonglong2*)&Bs[kk][64 + tx * 4];

                ull a2[8];
                PACK2(a2[0], alo.x); PACK2(a2[1], alo.y);
                PACK2(a2[2], alo.z); PACK2(a2[3], alo.w);
                PACK2(a2[4], ahi.x); PACK2(a2[5], ahi.y);
                PACK2(a2[6], ahi.z); PACK2(a2[7], ahi.w);

                ull b2[4];
                b2[0] = blo.x; b2[1] = blo.y; b2[2] = bhi.x; b2[3] = bhi.y;

#pragma unroll
                for (int r = 0; r < 8; r++) {
                    FMA2(acc[r][0], a2[r], b2[0]);
                    FMA2(acc[r][1], a2[r], b2[1]);
                    FMA2(acc[r][2], a2[r], b2[2]);
                    FMA2(acc[r][3], a2[r], b2[3]);
                }
            }
        }
    }

    // -------------------- epilogue --------------------
    float bias_lo[4], bias_hi[4];
    if (MODE >= 1) {
        float4 t = *(const float4*)&bias[bn + tx * 4];
        float4 u = *(const float4*)&bias[bn + 64 + tx * 4];
        bias_lo[0] = t.x; bias_lo[1] = t.y; bias_lo[2] = t.z; bias_lo[3] = t.w;
        bias_hi[0] = u.x; bias_hi[1] = u.y; bias_hi[2] = u.z; bias_hi[3] = u.w;
    }
    float scl = (MODE == 0) ? g_scale : 1.0f;

#pragma unroll
    for (int r = 0; r < 8; r++) {
        int row = bm + ((r < 4) ? (ty * 4 + r) : (64 + ty * 4 + (r - 4)));
        float v[8];
        UNPACK2(v[0], v[1], acc[r][0]);
        UNPACK2(v[2], v[3], acc[r][1]);
        UNPACK2(v[4], v[5], acc[r][2]);
        UNPACK2(v[6], v[7], acc[r][3]);

#pragma unroll
        for (int j = 0; j < 8; j++) {
            if (MODE == 0) {
                v[j] *= scl;
            } else {
                v[j] += (j < 4) ? bias_lo[j] : bias_hi[j - 4];
                if (MODE == 1 || MODE == 3) v[j] = fmaxf(v[j], 0.0f);
                else                        v[j] = tanhf(v[j]);
            }
        }

        float4 lo = make_float4(v[0], v[1], v[2], v[3]);
        float4 hi = make_float4(v[4], v[5], v[6], v[7]);

        if (MODE == 3) {
            if (bn < OUT_D) {
                float* p = C0 + (size_t)row * OUT_D + bn;
                *(float4*)(p + tx * 4)      = lo;
                *(float4*)(p + 64 + tx * 4) = hi;
            } else {
                float* p = C1 + (size_t)row * O2C_D + (bn - OUT_D);
                *(float4*)(p + tx * 4)      = lo;
                *(float4*)(p + 64 + tx * 4) = hi;
            }
        } else {
            float* p = C0 + (size_t)row * ldc0 + bn;
            *(float4*)(p + tx * 4)      = lo;
            *(float4*)(p + 64 + tx * 4) = hi;
        }
    }
}

// ---------------------------------------------------------------------------
// Launch
// ---------------------------------------------------------------------------
extern "C" void kernel_launch(void* const* d_in, const int* in_sizes, int n_in,
                              void* d_out, int out_size)
{
    const float* inputs = (const float*)d_in[0];   // (B, 512)
    const float* center = (const float*)d_in[1];   // (B, 512)
    const float* state  = (const float*)d_in[2];   // (B, 1024)
    const float* W_read = (const float*)d_in[3];   // (512, 256)
    const float* W_pre  = (const float*)d_in[4];   // (768, 1024)
    const float* b_pre  = (const float*)d_in[5];   // (1024)
    const float* Wx     = (const float*)d_in[6];   // (1024, 1024)
    const float* Wh     = (const float*)d_in[7];   // (1024, 1024)
    const float* b_rnn  = (const float*)d_in[8];   // (1024)
    const float* W_post = (const float*)d_in[9];   // (1024, 768)
    const float* b_post = (const float*)d_in[10];  // (768)

    float* out   = (float*)d_out;
    float* net   = out;                                    // (B, 512)
    float* toc   = out + (size_t)BATCH * OUT_D;            // (B, 256)
    float* h_new = out + (size_t)BATCH * (OUT_D + O2C_D);  // (B, 1024)

    static float* pWcomb = nullptr;
    static float* pRnnIn = nullptr;
    if (!pWcomb) {
        cudaGetSymbolAddress((void**)&pWcomb, g_Wcomb);
        cudaGetSymbolAddress((void**)&pRnnIn, g_rnn_in);
    }

    dim3 blk(256);

    // 1) scale = 1 / max(||W_read||, 1)
    norm_partial_kernel<<<256, 256>>>(W_read);
    norm_finish_kernel<<<1, 256>>>();

    // 2) W_comb(512x1024) = scale * W_read(512x256) @ W_pre[512:768,:](256x1024)
    gemm128_kernel<0><<<dim3(FF_D / 128, CENTER / 128), blk>>>(
        W_read, CTX_D, CTX_D,
        W_read, CTX_D,
        W_pre + (size_t)IN_D * FF_D, FF_D,
        W_pre + (size_t)IN_D * FF_D, FF_D,
        CTX_D,
        nullptr,
        pWcomb, FF_D, nullptr);

    // 3) rnn_in(Bx1024) = relu(inputs @ W_pre_top + center @ W_comb + b_pre)
    gemm128_kernel<1><<<dim3(FF_D / 128, BATCH / 128), blk>>>(
        inputs, IN_D, IN_D,
        center, CENTER,
        W_pre, FF_D,
        pWcomb, FF_D,
        IN_D + CENTER,   // 1024
        b_pre,
        pRnnIn, FF_D, nullptr);

    // 4) h_new(Bx1024) = tanh(rnn_in @ Wx + state @ Wh + b_rnn)
    gemm128_kernel<2><<<dim3(RNN_D / 128, BATCH / 128), blk>>>(
        pRnnIn, FF_D, FF_D,
        state, RNN_D,
        Wx, RNN_D,
        Wh, RNN_D,
        FF_D + RNN_D,    // 2048
        b_rnn,
        h_new, RNN_D, nullptr);

    // 5) split relu(h_new @ W_post + b_post) -> net (512) | toc (256)
    gemm128_kernel<3><<<dim3(TOT_D / 128, BATCH / 128), blk>>>(
        h_new, RNN_D, RNN_D,
        h_new, RNN_D,
        W_post, TOT_D,
        W_post, TOT_D,
        RNN_D,           // 1024
        b_post,
        net, OUT_D, toc);
}

// round 8
// speedup vs baseline: 1.9656x; 1.9656x over previous
#include <cuda_runtime.h>
#include <cuda_bf16.h>
#include <mma.h>
#include <cstdint>
#include <math.h>

using namespace nvcuda;

// ---------------------------------------------------------------------------
// Problem constants
// ---------------------------------------------------------------------------
#define BATCH  8192
#define IN_D   512
#define CTX_D  256
#define CENTER 512
#define FF_D   1024
#define RNN_D  1024
#define OUT_D  512
#define O2C_D  256
#define TOT_D  768

typedef unsigned long long ull;

// ---------------------------------------------------------------------------
// Scratch (__device__ globals; no cudaMalloc allowed)
// ---------------------------------------------------------------------------
__device__ float g_partials[256];
__device__ float g_scale;
__device__ float g_Wcomb[CENTER * FF_D];                // 512x1024 fp32

// Pre-transposed bf16 split weights, layout [N][Ktot] row-major.
__device__ __nv_bfloat16 g_B1h[FF_D * FF_D];            // 1024 x 1024
__device__ __nv_bfloat16 g_B1l[FF_D * FF_D];
__device__ __nv_bfloat16 g_B2h[RNN_D * (FF_D + RNN_D)]; // 1024 x 2048
__device__ __nv_bfloat16 g_B2l[RNN_D * (FF_D + RNN_D)];
__device__ __nv_bfloat16 g_B3h[TOT_D * RNN_D];          // 768 x 1024
__device__ __nv_bfloat16 g_B3l[TOT_D * RNN_D];

// Split activations, [B][Ktot] row-major.
__device__ __nv_bfloat16 g_X1h[(size_t)BATCH * FF_D];            // inputs|center
__device__ __nv_bfloat16 g_X1l[(size_t)BATCH * FF_D];
__device__ __nv_bfloat16 g_X2h[(size_t)BATCH * (FF_D + RNN_D)];  // rnn_in|state
__device__ __nv_bfloat16 g_X2l[(size_t)BATCH * (FF_D + RNN_D)];
__device__ __nv_bfloat16 g_X3h[(size_t)BATCH * RNN_D];           // h_new
__device__ __nv_bfloat16 g_X3l[(size_t)BATCH * RNN_D];

// ---------------------------------------------------------------------------
// Packed fp32x2 helpers (for the small fp32 precombine GEMM)
// ---------------------------------------------------------------------------
#define FMA2(accv, av, bv) \
    asm("fma.rn.f32x2 %0, %1, %2, %0;" : "+l"(accv) : "l"(av), "l"(bv))
#define PACK2(outv, x) \
    asm("mov.b64 %0, {%1, %2};" : "=l"(outv) \
        : "r"(__float_as_uint(x)), "r"(__float_as_uint(x)))
#define UNPACK2(lo, hi, p) do { \
    unsigned _lo, _hi; \
    asm("mov.b64 {%0, %1}, %2;" : "=r"(_lo), "=r"(_hi) : "l"(p)); \
    (lo) = __uint_as_float(_lo); (hi) = __uint_as_float(_hi); \
} while (0)

// ---------------------------------------------------------------------------
// Norm of W_read -> g_scale = 1 / max(||W_read||_F, 1)
// ---------------------------------------------------------------------------
__global__ void norm_partial_kernel(const float* __restrict__ W) {
    __shared__ float sh[256];
    const int n = CENTER * CTX_D;
    float s = 0.0f;
    for (int i = blockIdx.x * 256 + threadIdx.x; i < n; i += 256 * 256) {
        float v = W[i]; s += v * v;
    }
    sh[threadIdx.x] = s; __syncthreads();
    for (int off = 128; off > 0; off >>= 1) {
        if (threadIdx.x < off) sh[threadIdx.x] += sh[threadIdx.x + off];
        __syncthreads();
    }
    if (threadIdx.x == 0) g_partials[blockIdx.x] = sh[0];
}
__global__ void norm_finish_kernel() {
    __shared__ float sh[256];
    sh[threadIdx.x] = g_partials[threadIdx.x]; __syncthreads();
    for (int off = 128; off > 0; off >>= 1) {
        if (threadIdx.x < off) sh[threadIdx.x] += sh[threadIdx.x + off];
        __syncthreads();
    }
    if (threadIdx.x == 0) g_scale = 1.0f / fmaxf(sqrtf(sh[0]), 1.0f);
}

// ---------------------------------------------------------------------------
// fp32 FMA2 GEMM (proven) — W_comb precompute: C = g_scale * (A0 @ B0)
// ---------------------------------------------------------------------------
__global__ void __launch_bounds__(256, 2) gemm_wcomb_kernel(
    const float* __restrict__ A0, int lda0,
    const float* __restrict__ B0, int ldb0,
    int Ktot, float* __restrict__ C0, int ldc0)
{
    __shared__ float As[8][128];
    __shared__ float Bs[8][128];
    const int tid = threadIdx.x;
    const int tx = tid & 15, ty = tid >> 4;
    const int bm = blockIdx.y * 128, bn = blockIdx.x * 128;
    const int aRow = tid >> 1, aK = (tid & 1) * 4;
    const int bRow = tid >> 5, bCol = (tid & 31) * 4;

    ull acc[8][4];
#pragma unroll
    for (int r = 0; r < 8; r++)
#pragma unroll
        for (int j = 0; j < 4; j++) acc[r][j] = 0ull;

    const float* aPtr = A0 + (size_t)(bm + aRow) * lda0 + aK;
    const float* bPtr = B0 + (size_t)bRow * ldb0 + (bn + bCol);
#pragma unroll 1
    for (int k0 = 0; k0 < Ktot; k0 += 8) {
        float4 av = *(const float4*)(aPtr + k0);
        float4 bv = *(const float4*)(bPtr + (size_t)k0 * ldb0);
        __syncthreads();
        As[aK + 0][aRow] = av.x; As[aK + 1][aRow] = av.y;
        As[aK + 2][aRow] = av.z; As[aK + 3][aRow] = av.w;
        *(float4*)&Bs[bRow][bCol] = bv;
        __syncthreads();
#pragma unroll
        for (int kk = 0; kk < 8; kk++) {
            float4 alo = *(const float4*)&As[kk][ty * 4];
            float4 ahi = *(const float4*)&As[kk][64 + ty * 4];
            ulonglong2 blo = *(const ulonglong2*)&Bs[kk][tx * 4];
            ulonglong2 bhi = *(const ulonglong2*)&Bs[kk][64 + tx * 4];
            ull a2[8];
            PACK2(a2[0], alo.x); PACK2(a2[1], alo.y);
            PACK2(a2[2], alo.z); PACK2(a2[3], alo.w);
            PACK2(a2[4], ahi.x); PACK2(a2[5], ahi.y);
            PACK2(a2[6], ahi.z); PACK2(a2[7], ahi.w);
            ull b2[4] = {blo.x, blo.y, bhi.x, bhi.y};
#pragma unroll
            for (int r = 0; r < 8; r++) {
                FMA2(acc[r][0], a2[r], b2[0]);
                FMA2(acc[r][1], a2[r], b2[1]);
                FMA2(acc[r][2], a2[r], b2[2]);
                FMA2(acc[r][3], a2[r], b2[3]);
            }
        }
    }
    float scl = g_scale;
#pragma unroll
    for (int r = 0; r < 8; r++) {
        int row = bm + ((r < 4) ? (ty * 4 + r) : (64 + ty * 4 + (r - 4)));
        float v[8];
        UNPACK2(v[0], v[1], acc[r][0]); UNPACK2(v[2], v[3], acc[r][1]);
        UNPACK2(v[4], v[5], acc[r][2]); UNPACK2(v[6], v[7], acc[r][3]);
#pragma unroll
        for (int j = 0; j < 8; j++) v[j] *= scl;
        float* p = C0 + (size_t)row * ldc0 + bn;
        *(float4*)(p + tx * 4)      = make_float4(v[0], v[1], v[2], v[3]);
        *(float4*)(p + 64 + tx * 4) = make_float4(v[4], v[5], v[6], v[7]);
    }
}

// ---------------------------------------------------------------------------
// Weight transpose + bf16 split: src fp32 [Ksrc][N] -> dst hi/lo bf16 [N][Kfull]
// ---------------------------------------------------------------------------
__global__ void wconv_kernel(const float* __restrict__ src, int N, int Ksrc,
                             __nv_bfloat16* __restrict__ dh,
                             __nv_bfloat16* __restrict__ dl,
                             int Kfull, int koff)
{
    __shared__ float t[32][33];
    const int n0 = blockIdx.x * 32;
    const int k0 = blockIdx.y * 32;
    const int tx = threadIdx.x, ty = threadIdx.y; // 32 x 8
#pragma unroll
    for (int i = 0; i < 4; i++) {
        int k = k0 + ty + 8 * i;
        t[ty + 8 * i][tx] = src[(size_t)k * N + n0 + tx];
    }
    __syncthreads();
#pragma unroll
    for (int i = 0; i < 4; i++) {
        int n = n0 + ty + 8 * i;
        float v = t[tx][ty + 8 * i];
        __nv_bfloat16 h = __float2bfloat16_rn(v);
        __nv_bfloat16 l = __float2bfloat16_rn(v - __bfloat162float(h));
        size_t o = (size_t)n * Kfull + koff + k0 + tx;
        dh[o] = h; dl[o] = l;
    }
}

// ---------------------------------------------------------------------------
// Activation split: src fp32 [M][Ksrc] row-major -> hi/lo bf16 [M][Kfull]@koff
// ---------------------------------------------------------------------------
__global__ void aconv_kernel(const float* __restrict__ src, int Ksrc,
                             __nv_bfloat16* __restrict__ dh,
                             __nv_bfloat16* __restrict__ dl,
                             int Kfull, int koff, int total4)
{
    int idx = blockIdx.x * 256 + threadIdx.x;
    if (idx >= total4) return;
    int kq  = Ksrc >> 2;
    int row = idx / kq;
    int c4  = (idx - row * kq) * 4;
    float4 v = *(const float4*)(src + (size_t)row * Ksrc + c4);
    __nv_bfloat162 h01 = __floats2bfloat162_rn(v.x, v.y);
    __nv_bfloat162 h23 = __floats2bfloat162_rn(v.z, v.w);
    __nv_bfloat162 l01 = __floats2bfloat162_rn(v.x - __bfloat162float(h01.x),
                                               v.y - __bfloat162float(h01.y));
    __nv_bfloat162 l23 = __floats2bfloat162_rn(v.z - __bfloat162float(h23.x),
                                               v.w - __bfloat162float(h23.y));
    size_t o = (size_t)row * Kfull + koff + c4;
    *(uint2*)(dh + o) = make_uint2(*(uint32_t*)&h01, *(uint32_t*)&h23);
    *(uint2*)(dl + o) = make_uint2(*(uint32_t*)&l01, *(uint32_t*)&l23);
}

// ---------------------------------------------------------------------------
// Split-bf16 WMMA GEMM, 128x128 tile, K-chunk 64, 256 threads, 2 CTAs/SM.
//   acc = Ah@Bh^T + Ah@Bl^T + Al@Bh^T   (fp32 accum)
//   out = act(acc + bias)
// MODE 1: relu; write bf16 hi/lo aux only          (rnn_in -> X2)
// MODE 2: tanh; write fp32 C0 + bf16 hi/lo aux     (h_new -> out, X3)
// MODE 3: relu; write fp32 split C0/C1             (net | toc)
// ---------------------------------------------------------------------------
#define KC    64
#define KPAD  72          // elements; 144 bytes row stride
#define TILEB (128 * KPAD * 2)              // 18432 bytes per matrix
#define SOFF_BIAS 0
#define SOFF_TILE 1024
#define SMEM_DYN  (SOFF_TILE + 4 * TILEB)   // 1024 + 73728 = 74752

template <int MODE>
__global__ void __launch_bounds__(256, 2) tgemm_kernel(
    const __nv_bfloat16* __restrict__ Agh,
    const __nv_bfloat16* __restrict__ Agl,
    const __nv_bfloat16* __restrict__ Bgh,
    const __nv_bfloat16* __restrict__ Bgl,
    int Ktot,
    const float* __restrict__ bias,
    float* __restrict__ C0, int ldc0,
    float* __restrict__ C1,
    __nv_bfloat16* __restrict__ Xh,
    __nv_bfloat16* __restrict__ Xl,
    int ldx)
{
    extern __shared__ char smem[];
    char* sAh = smem + SOFF_TILE;
    char* sAl = sAh + TILEB;
    char* sBh = sAl + TILEB;
    char* sBl = sBh + TILEB;

    const int tid = threadIdx.x;
    const int wid = tid >> 5;
    const int bm = blockIdx.y * 128;
    const int bn = blockIdx.x * 128;
    const int warpM = (wid >> 2) * 64;   // 0 | 64
    const int warpN = (wid & 3) * 32;    // 0,32,64,96

    if (tid < 128) ((float*)(smem + SOFF_BIAS))[tid] = bias[bn + tid];

    wmma::fragment<wmma::accumulator, 16, 16, 16, float> cf[4][2];
#pragma unroll
    for (int m = 0; m < 4; m++)
#pragma unroll
        for (int n = 0; n < 2; n++) wmma::fill_fragment(cf[m][n], 0.0f);

#pragma unroll 1
    for (int koff = 0; koff < Ktot; koff += KC) {
        __syncthreads();   // previous chunk's compute done
        // ---- load chunk: 4 matrices, 128x64 bf16 each ----
#pragma unroll
        for (int t = 0; t < 4; t++) {
            int idx = tid + t * 256;       // 0..1023
            int row = idx >> 3;
            int kq  = (idx & 7) * 8;       // element offset
            int so  = row * (KPAD * 2) + kq * 2;  // byte offset
            size_t ga = (size_t)(bm + row) * Ktot + koff + kq;
            size_t gb = (size_t)(bn + row) * Ktot + koff + kq;
            *(uint4*)(sAh + so) = *(const uint4*)(Agh + ga);
            *(uint4*)(sAl + so) = *(const uint4*)(Agl + ga);
            *(uint4*)(sBh + so) = *(const uint4*)(Bgh + gb);
            *(uint4*)(sBl + so) = *(const uint4*)(Bgl + gb);
        }
        __syncthreads();

        // ---- compute: 4 k-slices x 3 combos ----
#pragma unroll
        for (int ks = 0; ks < 4; ks++) {
            const int k0 = ks * 16;
#pragma unroll
            for (int combo = 0; combo < 3; combo++) {
                const __nv_bfloat16* Asel = (const __nv_bfloat16*)
                    ((combo == 2) ? sAl : sAh);
                const __nv_bfloat16* Bsel = (const __nv_bfloat16*)
                    ((combo == 1) ? sBl : sBh);
                wmma::fragment<wmma::matrix_b, 16, 16, 16,
                               __nv_bfloat16, wmma::col_major> bf0, bf1;
                wmma::load_matrix_sync(bf0,
                    Bsel + (warpN +  0) * KPAD + k0, KPAD);
                wmma::load_matrix_sync(bf1,
                    Bsel + (warpN + 16) * KPAD + k0, KPAD);
#pragma unroll
                for (int m = 0; m < 4; m++) {
                    wmma::fragment<wmma::matrix_a, 16, 16, 16,
                                   __nv_bfloat16, wmma::row_major> af;
                    wmma::load_matrix_sync(af,
                        Asel + (warpM + m * 16) * KPAD + k0, KPAD);
                    wmma::mma_sync(cf[m][0], af, bf0, cf[m][0]);
                    wmma::mma_sync(cf[m][1], af, bf1, cf[m][1]);
                }
            }
        }
    }

    // ---- epilogue: stage fp32 through SMEM ----
    __syncthreads();
    float* stg = (float*)(smem + SOFF_TILE);   // [128][132]
#pragma unroll
    for (int m = 0; m < 4; m++)
#pragma unroll
        for (int n = 0; n < 2; n++)
            wmma::store_matrix_sync(
                stg + (warpM + m * 16) * 132 + warpN + n * 16,
                cf[m][n], 132, wmma::mem_row_major);
    __syncthreads();

    {
        const float* bias_s = (const float*)(smem + SOFF_BIAS);
        const int r  = tid >> 1;            // 0..127
        const int ch = (tid & 1) * 64;      // col half
        const int grow = bm + r;
#pragma unroll
        for (int c0 = 0; c0 < 64; c0 += 8) {
            float v[8];
#pragma unroll
            for (int j = 0; j < 8; j += 4) {
                float4 x = *(const float4*)(stg + r * 132 + ch + c0 + j);
                v[j + 0] = x.x; v[j + 1] = x.y; v[j + 2] = x.z; v[j + 3] = x.w;
            }
#pragma unroll
            for (int j = 0; j < 8; j++) {
                float x = v[j] + bias_s[ch + c0 + j];
                if (MODE == 2) v[j] = tanhf(x);
                else           v[j] = fmaxf(x, 0.0f);
            }
            // fp32 outputs
            if (MODE == 2) {
                float* p = C0 + (size_t)grow * ldc0 + bn + ch + c0;
                *(float4*)(p)     = make_float4(v[0], v[1], v[2], v[3]);
                *(float4*)(p + 4) = make_float4(v[4], v[5], v[6], v[7]);
            } else if (MODE == 3) {
                float* p;
                if (bn < OUT_D) p = C0 + (size_t)grow * OUT_D + bn + ch + c0;
                else            p = C1 + (size_t)grow * O2C_D + (bn - OUT_D) + ch + c0;
                *(float4*)(p)     = make_float4(v[0], v[1], v[2], v[3]);
                *(float4*)(p + 4) = make_float4(v[4], v[5], v[6], v[7]);
            }
            // bf16 hi/lo aux for next layer
            if (MODE == 1 || MODE == 2) {
                unsigned short h[8], l[8];
#pragma unroll
                for (int j = 0; j < 8; j++) {
                    __nv_bfloat16 hb = __float2bfloat16_rn(v[j]);
                    __nv_bfloat16 lb =
                        __float2bfloat16_rn(v[j] - __bfloat162float(hb));
                    h[j] = *(unsigned short*)&hb;
                    l[j] = *(unsigned short*)&lb;
                }
                size_t o = (size_t)grow * ldx + bn + ch + c0;
                *(uint4*)(Xh + o) = *(uint4*)h;
                *(uint4*)(Xl + o) = *(uint4*)l;
            }
        }
    }
}

// ---------------------------------------------------------------------------
// Launch
// ---------------------------------------------------------------------------
extern "C" void kernel_launch(void* const* d_in, const int* in_sizes, int n_in,
                              void* d_out, int out_size)
{
    const float* inputs = (const float*)d_in[0];   // (B, 512)
    const float* center = (const float*)d_in[1];   // (B, 512)
    const float* state  = (const float*)d_in[2];   // (B, 1024)
    const float* W_read = (const float*)d_in[3];   // (512, 256)
    const float* W_pre  = (const float*)d_in[4];   // (768, 1024)
    const float* b_pre  = (const float*)d_in[5];   // (1024)
    const float* Wx     = (const float*)d_in[6];   // (1024, 1024)
    const float* Wh     = (const float*)d_in[7];   // (1024, 1024)
    const float* b_rnn  = (const float*)d_in[8];   // (1024)
    const float* W_post = (const float*)d_in[9];   // (1024, 768)
    const float* b_post = (const float*)d_in[10];  // (768)

    float* out   = (float*)d_out;
    float* net   = out;
    float* toc   = out + (size_t)BATCH * OUT_D;
    float* h_new = out + (size_t)BATCH * (OUT_D + O2C_D);

    static float* pWcomb = nullptr;
    static __nv_bfloat16 *pB1h, *pB1l, *pB2h, *pB2l, *pB3h, *pB3l;
    static __nv_bfloat16 *pX1h, *pX1l, *pX2h, *pX2l, *pX3h, *pX3l;
    static bool init_done = false;
    if (!init_done) {
        cudaGetSymbolAddress((void**)&pWcomb, g_Wcomb);
        cudaGetSymbolAddress((void**)&pB1h, g_B1h);
        cudaGetSymbolAddress((void**)&pB1l, g_B1l);
        cudaGetSymbolAddress((void**)&pB2h, g_B2h);
        cudaGetSymbolAddress((void**)&pB2l, g_B2l);
        cudaGetSymbolAddress((void**)&pB3h, g_B3h);
        cudaGetSymbolAddress((void**)&pB3l, g_B3l);
        cudaGetSymbolAddress((void**)&pX1h, g_X1h);
        cudaGetSymbolAddress((void**)&pX1l, g_X1l);
        cudaGetSymbolAddress((void**)&pX2h, g_X2h);
        cudaGetSymbolAddress((void**)&pX2l, g_X2l);
        cudaGetSymbolAddress((void**)&pX3h, g_X3h);
        cudaGetSymbolAddress((void**)&pX3l, g_X3l);
        cudaFuncSetAttribute(tgemm_kernel<1>,
            cudaFuncAttributeMaxDynamicSharedMemorySize, SMEM_DYN);
        cudaFuncSetAttribute(tgemm_kernel<2>,
            cudaFuncAttributeMaxDynamicSharedMemorySize, SMEM_DYN);
        cudaFuncSetAttribute(tgemm_kernel<3>,
            cudaFuncAttributeMaxDynamicSharedMemorySize, SMEM_DYN);
        init_done = true;
    }

    dim3 blk(256);
    dim3 tblk(32, 8);

    // 1) scale = 1 / max(||W_read||, 1)
    norm_partial_kernel<<<256, 256>>>(W_read);
    norm_finish_kernel<<<1, 256>>>();

    // 2) W_comb = scale * W_read @ W_pre[512:768,:]   [fp32, proven kernel]
    gemm_wcomb_kernel<<<dim3(FF_D / 128, CENTER / 128), blk>>>(
        W_read, CTX_D, W_pre + (size_t)IN_D * FF_D, FF_D, CTX_D, pWcomb, FF_D);

    // 3) weight transpose + split
    wconv_kernel<<<dim3(FF_D / 32, IN_D / 32),   tblk>>>(W_pre,  FF_D, IN_D,
                                                         pB1h, pB1l, FF_D, 0);
    wconv_kernel<<<dim3(FF_D / 32, CENTER / 32), tblk>>>(pWcomb, FF_D, CENTER,
                                                         pB1h, pB1l, FF_D, IN_D);
    wconv_kernel<<<dim3(RNN_D / 32, FF_D / 32),  tblk>>>(Wx, RNN_D, FF_D,
                                                         pB2h, pB2l, FF_D + RNN_D, 0);
    wconv_kernel<<<dim3(RNN_D / 32, RNN_D / 32), tblk>>>(Wh, RNN_D, RNN_D,
                                                         pB2h, pB2l, FF_D + RNN_D, FF_D);
    wconv_kernel<<<dim3(TOT_D / 32, RNN_D / 32), tblk>>>(W_post, TOT_D, RNN_D,
                                                         pB3h, pB3l, RNN_D, 0);

    // 4) activation splits: inputs|center -> X1, state -> X2@1024
    {
        int t4 = BATCH * IN_D / 4;
        aconv_kernel<<<(t4 + 255) / 256, 256>>>(inputs, IN_D,
                                                pX1h, pX1l, FF_D, 0, t4);
        aconv_kernel<<<(t4 + 255) / 256, 256>>>(center, CENTER,
                                                pX1h, pX1l, FF_D, IN_D, t4);
        int t4s = BATCH * RNN_D / 4;
        aconv_kernel<<<(t4s + 255) / 256, 256>>>(state, RNN_D,
                                                 pX2h, pX2l, FF_D + RNN_D, FF_D, t4s);
    }

    // 5) rnn_in = relu(X1 @ B1^T + b_pre)  -> split into X2[:, :1024]
    tgemm_kernel<1><<<dim3(FF_D / 128, BATCH / 128), blk, SMEM_DYN>>>(
        pX1h, pX1l, pB1h, pB1l, FF_D, b_pre,
        nullptr, 0, nullptr, pX2h, pX2l, FF_D + RNN_D);

    // 6) h_new = tanh(X2 @ B2^T + b_rnn)   -> fp32 out + split into X3
    tgemm_kernel<2><<<dim3(RNN_D / 128, BATCH / 128), blk, SMEM_DYN>>>(
        pX2h, pX2l, pB2h, pB2l, FF_D + RNN_D, b_rnn,
        h_new, RNN_D, nullptr, pX3h, pX3l, RNN_D);

    // 7) [net | toc] = relu(X3 @ B3^T + b_post)
    tgemm_kernel<3><<<dim3(TOT_D / 128, BATCH / 128), blk, SMEM_DYN>>>(
        pX3h, pX3l, pB3h, pB3l, RNN_D, b_post,
        net, OUT_D, toc, nullptr, nullptr, 0);
}

// round 12
// speedup vs baseline: 2.9292x; 1.4902x over previous
#include <cuda_runtime.h>
#include <cuda_fp16.h>
#include <cuda_bf16.h>
#include <mma.h>
#include <cstdint>
#include <math.h>

using namespace nvcuda;

// ---------------------------------------------------------------------------
// Problem constants
// ---------------------------------------------------------------------------
#define BATCH  8192
#define IN_D   512
#define CTX_D  256
#define CENTER 512
#define FF_D   1024
#define RNN_D  1024
#define OUT_D  512
#define O2C_D  256
#define TOT_D  768

typedef unsigned long long ull;

// ---------------------------------------------------------------------------
// Scratch (__device__ globals; no cudaMalloc allowed)
// ---------------------------------------------------------------------------
__device__ float g_partials[256];
__device__ float g_scale;
__device__ float g_Wcomb[CENTER * FF_D];                // 512x1024 fp32

// Pre-transposed fp16 split weights, layout [N][Ktot] row-major.
__device__ __half g_B1h[FF_D * FF_D];                   // 1024 x 1024
__device__ __half g_B1l[FF_D * FF_D];
__device__ __half g_B2h[RNN_D * (FF_D + RNN_D)];        // 1024 x 2048
__device__ __half g_B2l[RNN_D * (FF_D + RNN_D)];
__device__ __half g_B3h[TOT_D * RNN_D];                 // 768 x 1024
__device__ __half g_B3l[TOT_D * RNN_D];

// fp16 activations, [B][Ktot] row-major (unsplit).
__device__ __half g_X1[(size_t)BATCH * FF_D];            // inputs|center
__device__ __half g_X2[(size_t)BATCH * (FF_D + RNN_D)];  // rnn_in|state
__device__ __half g_X3[(size_t)BATCH * RNN_D];           // h_new

// ---------------------------------------------------------------------------
// Packed fp32x2 helpers (for the small fp32 precombine GEMM)
// ---------------------------------------------------------------------------
#define FMA2(accv, av, bv) \
    asm("fma.rn.f32x2 %0, %1, %2, %0;" : "+l"(accv) : "l"(av), "l"(bv))
#define PACK2(outv, x) \
    asm("mov.b64 %0, {%1, %2};" : "=l"(outv) \
        : "r"(__float_as_uint(x)), "r"(__float_as_uint(x)))
#define UNPACK2(lo, hi, p) do { \
    unsigned _lo, _hi; \
    asm("mov.b64 {%0, %1}, %2;" : "=r"(_lo), "=r"(_hi) : "l"(p)); \
    (lo) = __uint_as_float(_lo); (hi) = __uint_as_float(_hi); \
} while (0)

// ---------------------------------------------------------------------------
// Norm of W_read -> g_scale = 1 / max(||W_read||_F, 1)
// ---------------------------------------------------------------------------
__global__ void norm_partial_kernel(const float* __restrict__ W) {
    __shared__ float sh[256];
    const int n = CENTER * CTX_D;
    float s = 0.0f;
    for (int i = blockIdx.x * 256 + threadIdx.x; i < n; i += 256 * 256) {
        float v = W[i]; s += v * v;
    }
    sh[threadIdx.x] = s; __syncthreads();
    for (int off = 128; off > 0; off >>= 1) {
        if (threadIdx.x < off) sh[threadIdx.x] += sh[threadIdx.x + off];
        __syncthreads();
    }
    if (threadIdx.x == 0) g_partials[blockIdx.x] = sh[0];
}
__global__ void norm_finish_kernel() {
    __shared__ float sh[256];
    sh[threadIdx.x] = g_partials[threadIdx.x]; __syncthreads();
    for (int off = 128; off > 0; off >>= 1) {
        if (threadIdx.x < off) sh[threadIdx.x] += sh[threadIdx.x + off];
        __syncthreads();
    }
    if (threadIdx.x == 0) g_scale = 1.0f / fmaxf(sqrtf(sh[0]), 1.0f);
}

// ---------------------------------------------------------------------------
// fp32 FMA2 GEMM (proven) — W_comb precompute: C = g_scale * (A0 @ B0)
// ---------------------------------------------------------------------------
__global__ void __launch_bounds__(256, 2) gemm_wcomb_kernel(
    const float* __restrict__ A0, int lda0,
    const float* __restrict__ B0, int ldb0,
    int Ktot, float* __restrict__ C0, int ldc0)
{
    __shared__ float As[8][128];
    __shared__ float Bs[8][128];
    const int tid = threadIdx.x;
    const int tx = tid & 15, ty = tid >> 4;
    const int bm = blockIdx.y * 128, bn = blockIdx.x * 128;
    const int aRow = tid >> 1, aK = (tid & 1) * 4;
    const int bRow = tid >> 5, bCol = (tid & 31) * 4;

    ull acc[8][4];
#pragma unroll
    for (int r = 0; r < 8; r++)
#pragma unroll
        for (int j = 0; j < 4; j++) acc[r][j] = 0ull;

    const float* aPtr = A0 + (size_t)(bm + aRow) * lda0 + aK;
    const float* bPtr = B0 + (size_t)bRow * ldb0 + (bn + bCol);
#pragma unroll 1
    for (int k0 = 0; k0 < Ktot; k0 += 8) {
        float4 av = *(const float4*)(aPtr + k0);
        float4 bv = *(const float4*)(bPtr + (size_t)k0 * ldb0);
        __syncthreads();
        As[aK + 0][aRow] = av.x; As[aK + 1][aRow] = av.y;
        As[aK + 2][aRow] = av.z; As[aK + 3][aRow] = av.w;
        *(float4*)&Bs[bRow][bCol] = bv;
        __syncthreads();
#pragma unroll
        for (int kk = 0; kk < 8; kk++) {
            float4 alo = *(const float4*)&As[kk][ty * 4];
            float4 ahi = *(const float4*)&As[kk][64 + ty * 4];
            ulonglong2 blo = *(const ulonglong2*)&Bs[kk][tx * 4];
            ulonglong2 bhi = *(const ulonglong2*)&Bs[kk][64 + tx * 4];
            ull a2[8];
            PACK2(a2[0], alo.x); PACK2(a2[1], alo.y);
            PACK2(a2[2], alo.z); PACK2(a2[3], alo.w);
            PACK2(a2[4], ahi.x); PACK2(a2[5], ahi.y);
            PACK2(a2[6], ahi.z); PACK2(a2[7], ahi.w);
            ull b2[4] = {blo.x, blo.y, bhi.x, bhi.y};
#pragma unroll
            for (int r = 0; r < 8; r++) {
                FMA2(acc[r][0], a2[r], b2[0]);
                FMA2(acc[r][1], a2[r], b2[1]);
                FMA2(acc[r][2], a2[r], b2[2]);
                FMA2(acc[r][3], a2[r], b2[3]);
            }
        }
    }
    float scl = g_scale;
#pragma unroll
    for (int r = 0; r < 8; r++) {
        int row = bm + ((r < 4) ? (ty * 4 + r) : (64 + ty * 4 + (r - 4)));
        float v[8];
        UNPACK2(v[0], v[1], acc[r][0]); UNPACK2(v[2], v[3], acc[r][1]);
        UNPACK2(v[4], v[5], acc[r][2]); UNPACK2(v[6], v[7], acc[r][3]);
#pragma unroll
        for (int j = 0; j < 8; j++) v[j] *= scl;
        float* p = C0 + (size_t)row * ldc0 + bn;
        *(float4*)(p + tx * 4)      = make_float4(v[0], v[1], v[2], v[3]);
        *(float4*)(p + 64 + tx * 4) = make_float4(v[4], v[5], v[6], v[7]);
    }
}

// ---------------------------------------------------------------------------
// Weight transpose + fp16 split: src fp32 [Ksrc][N] -> dst hi/lo fp16 [N][Kfull]
// ---------------------------------------------------------------------------
__global__ void wconv_kernel(const float* __restrict__ src, int N, int Ksrc,
                             __half* __restrict__ dh,
                             __half* __restrict__ dl,
                             int Kfull, int koff)
{
    __shared__ float t[32][33];
    const int n0 = blockIdx.x * 32;
    const int k0 = blockIdx.y * 32;
    const int tx = threadIdx.x, ty = threadIdx.y; // 32 x 8
#pragma unroll
    for (int i = 0; i < 4; i++) {
        int k = k0 + ty + 8 * i;
        t[ty + 8 * i][tx] = src[(size_t)k * N + n0 + tx];
    }
    __syncthreads();
#pragma unroll
    for (int i = 0; i < 4; i++) {
        int n = n0 + ty + 8 * i;
        float v = t[tx][ty + 8 * i];
        __half h = __float2half_rn(v);
        __half l = __float2half_rn(v - __half2float(h));
        size_t o = (size_t)n * Kfull + koff + k0 + tx;
        dh[o] = h; dl[o] = l;
    }
}

// ---------------------------------------------------------------------------
// Activation convert: src fp32 [M][Ksrc] -> fp16 [M][Kfull] at column koff
// ---------------------------------------------------------------------------
__global__ void aconv_kernel(const float* __restrict__ src, int Ksrc,
                             __half* __restrict__ dst,
                             int Kfull, int koff, int total4)
{
    int idx = blockIdx.x * 256 + threadIdx.x;
    if (idx >= total4) return;
    int kq  = Ksrc >> 2;
    int row = idx / kq;
    int c4  = (idx - row * kq) * 4;
    float4 v = *(const float4*)(src + (size_t)row * Ksrc + c4);
    __half2 h01 = __floats2half2_rn(v.x, v.y);
    __half2 h23 = __floats2half2_rn(v.z, v.w);
    size_t o = (size_t)row * Kfull + koff + c4;
    *(uint2*)(dst + o) = make_uint2(*(uint32_t*)&h01, *(uint32_t*)&h23);
}

// ---------------------------------------------------------------------------
// fp16 WMMA GEMM (A unsplit, B split hi/lo), 128x128 tile, K-chunk 64,
// 256 threads, 2 CTAs/SM.
//   acc = A@Bh^T + A@Bl^T   (fp32 accum; both into the same accumulator)
//   out = act(acc + bias)
// MODE 1: relu; write fp16 act only          (rnn_in -> X2)
// MODE 2: tanh; write fp32 C0 + fp16 act     (h_new -> out, X3)
// MODE 3: relu; write fp32 split C0/C1       (net | toc)
// ---------------------------------------------------------------------------
#define KC    64
#define KPAD  72          // elements; 144 bytes row stride
#define TILEB (128 * KPAD * 2)              // 18432 bytes per matrix
#define SOFF_BIAS 0
#define SOFF_TILE 1024
#define SMEM_DYN  (SOFF_TILE + 3 * TILEB)   // 1024 + 55296 = 56320

template <int MODE>
__global__ void __launch_bounds__(256, 2) tgemm_kernel(
    const __half* __restrict__ Ag,
    const __half* __restrict__ Bgh,
    const __half* __restrict__ Bgl,
    int Ktot,
    const float* __restrict__ bias,
    float* __restrict__ C0, int ldc0,
    float* __restrict__ C1,
    __half* __restrict__ Xo,
    int ldx)
{
    extern __shared__ char smem[];
    char* sA  = smem + SOFF_TILE;
    char* sBh = sA + TILEB;
    char* sBl = sBh + TILEB;

    const int tid = threadIdx.x;
    const int wid = tid >> 5;
    const int bm = blockIdx.y * 128;
    const int bn = blockIdx.x * 128;
    const int warpM = (wid >> 2) * 64;   // 0 | 64
    const int warpN = (wid & 3) * 32;    // 0,32,64,96

    if (tid < 128) ((float*)(smem + SOFF_BIAS))[tid] = bias[bn + tid];

    wmma::fragment<wmma::accumulator, 16, 16, 16, float> cf[4][2];
#pragma unroll
    for (int m = 0; m < 4; m++)
#pragma unroll
        for (int n = 0; n < 2; n++) wmma::fill_fragment(cf[m][n], 0.0f);

#pragma unroll 1
    for (int koff = 0; koff < Ktot; koff += KC) {
        __syncthreads();   // previous chunk's compute done
        // ---- load chunk: 3 matrices, 128x64 fp16 each ----
#pragma unroll
        for (int t = 0; t < 4; t++) {
            int idx = tid + t * 256;       // 0..1023
            int row = idx >> 3;
            int kq  = (idx & 7) * 8;       // element offset
            int so  = row * (KPAD * 2) + kq * 2;  // byte offset
            size_t ga = (size_t)(bm + row) * Ktot + koff + kq;
            size_t gb = (size_t)(bn + row) * Ktot + koff + kq;
            *(uint4*)(sA  + so) = *(const uint4*)(Ag  + ga);
            *(uint4*)(sBh + so) = *(const uint4*)(Bgh + gb);
            *(uint4*)(sBl + so) = *(const uint4*)(Bgl + gb);
        }
        __syncthreads();

        // ---- compute: 4 k-slices, frag loads hoisted ----
#pragma unroll
        for (int ks = 0; ks < 4; ks++) {
            const int k0 = ks * 16;
            wmma::fragment<wmma::matrix_b, 16, 16, 16,
                           __half, wmma::col_major> bh0, bh1, bl0, bl1;
            wmma::load_matrix_sync(bh0,
                (const __half*)sBh + (warpN +  0) * KPAD + k0, KPAD);
            wmma::load_matrix_sync(bh1,
                (const __half*)sBh + (warpN + 16) * KPAD + k0, KPAD);
            wmma::load_matrix_sync(bl0,
                (const __half*)sBl + (warpN +  0) * KPAD + k0, KPAD);
            wmma::load_matrix_sync(bl1,
                (const __half*)sBl + (warpN + 16) * KPAD + k0, KPAD);
#pragma unroll
            for (int m = 0; m < 4; m++) {
                wmma::fragment<wmma::matrix_a, 16, 16, 16,
                               __half, wmma::row_major> af;
                wmma::load_matrix_sync(af,
                    (const __half*)sA + (warpM + m * 16) * KPAD + k0, KPAD);
                wmma::mma_sync(cf[m][0], af, bh0, cf[m][0]);
                wmma::mma_sync(cf[m][0], af, bl0, cf[m][0]);
                wmma::mma_sync(cf[m][1], af, bh1, cf[m][1]);
                wmma::mma_sync(cf[m][1], af, bl1, cf[m][1]);
            }
        }
    }

    // ---- epilogue: stage fp32 through SMEM ----
    __syncthreads();
    float* stg = (float*)(smem + SOFF_TILE);   // [128][132] (66KB < 3 tiles? no:
                                               // 128*132*4 = 67584 > 55296!)
    // Use a two-half staged epilogue to fit: stage 64 rows at a time.
#pragma unroll 1
    for (int half = 0; half < 2; half++) {
        // warps with warpM matching this half store their fragments
        if ((warpM >> 6) == half) {
#pragma unroll
            for (int m = 0; m < 4; m++)
#pragma unroll
                for (int n = 0; n < 2; n++)
                    wmma::store_matrix_sync(
                        stg + ((warpM & 63) + m * 16) * 132 + warpN + n * 16,
                        cf[m][n], 132, wmma::mem_row_major);
        }
        __syncthreads();

        const float* bias_s = (const float*)(smem + SOFF_BIAS);
        const int r  = tid >> 1;            // 0..127 local row in this half*? no:
        // 256 threads cover 64 rows x 2 col-halves: r in [0,64)
        const int rr = tid >> 2;            // 0..63
        const int ch = (tid & 3) * 32;      // col quarter
        const int grow = bm + half * 64 + rr;
        (void)r;
#pragma unroll
        for (int c0 = 0; c0 < 32; c0 += 8) {
            float v[8];
#pragma unroll
            for (int j = 0; j < 8; j += 4) {
                float4 x = *(const float4*)(stg + rr * 132 + ch + c0 + j);
                v[j + 0] = x.x; v[j + 1] = x.y; v[j + 2] = x.z; v[j + 3] = x.w;
            }
#pragma unroll
            for (int j = 0; j < 8; j++) {
                float x = v[j] + bias_s[ch + c0 + j];
                if (MODE == 2) v[j] = tanhf(x);
                else           v[j] = fmaxf(x, 0.0f);
            }
            // fp32 outputs
            if (MODE == 2) {
                float* p = C0 + (size_t)grow * ldc0 + bn + ch + c0;
                *(float4*)(p)     = make_float4(v[0], v[1], v[2], v[3]);
                *(float4*)(p + 4) = make_float4(v[4], v[5], v[6], v[7]);
            } else if (MODE == 3) {
                float* p;
                if (bn < OUT_D) p = C0 + (size_t)grow * OUT_D + bn + ch + c0;
                else            p = C1 + (size_t)grow * O2C_D + (bn - OUT_D) + ch + c0;
                *(float4*)(p)     = make_float4(v[0], v[1], v[2], v[3]);
                *(float4*)(p + 4) = make_float4(v[4], v[5], v[6], v[7]);
            }
            // fp16 activation for next layer
            if (MODE == 1 || MODE == 2) {
                __half2 h01 = __floats2half2_rn(v[0], v[1]);
                __half2 h23 = __floats2half2_rn(v[2], v[3]);
                __half2 h45 = __floats2half2_rn(v[4], v[5]);
                __half2 h67 = __floats2half2_rn(v[6], v[7]);
                size_t o = (size_t)grow * ldx + bn + ch + c0;
                *(uint4*)(Xo + o) = make_uint4(
                    *(uint32_t*)&h01, *(uint32_t*)&h23,
                    *(uint32_t*)&h45, *(uint32_t*)&h67);
            }
        }
        __syncthreads();
    }
}

// ---------------------------------------------------------------------------
// Launch
// ---------------------------------------------------------------------------
extern "C" void kernel_launch(void* const* d_in, const int* in_sizes, int n_in,
                              void* d_out, int out_size)
{
    const float* inputs = (const float*)d_in[0];   // (B, 512)
    const float* center = (const float*)d_in[1];   // (B, 512)
    const float* state  = (const float*)d_in[2];   // (B, 1024)
    const float* W_read = (const float*)d_in[3];   // (512, 256)
    const float* W_pre  = (const float*)d_in[4];   // (768, 1024)
    const float* b_pre  = (const float*)d_in[5];   // (1024)
    const float* Wx     = (const float*)d_in[6];   // (1024, 1024)
    const float* Wh     = (const float*)d_in[7];   // (1024, 1024)
    const float* b_rnn  = (const float*)d_in[8];   // (1024)
    const float* W_post = (const float*)d_in[9];   // (1024, 768)
    const float* b_post = (const float*)d_in[10];  // (768)

    float* out   = (float*)d_out;
    float* net   = out;
    float* toc   = out + (size_t)BATCH * OUT_D;
    float* h_new = out + (size_t)BATCH * (OUT_D + O2C_D);

    static float* pWcomb = nullptr;
    static __half *pB1h, *pB1l, *pB2h, *pB2l, *pB3h, *pB3l;
    static __half *pX1, *pX2, *pX3;
    static bool init_done = false;
    if (!init_done) {
        cudaGetSymbolAddress((void**)&pWcomb, g_Wcomb);
        cudaGetSymbolAddress((void**)&pB1h, g_B1h);
        cudaGetSymbolAddress((void**)&pB1l, g_B1l);
        cudaGetSymbolAddress((void**)&pB2h, g_B2h);
        cudaGetSymbolAddress((void**)&pB2l, g_B2l);
        cudaGetSymbolAddress((void**)&pB3h, g_B3h);
        cudaGetSymbolAddress((void**)&pB3l, g_B3l);
        cudaGetSymbolAddress((void**)&pX1, g_X1);
        cudaGetSymbolAddress((void**)&pX2, g_X2);
        cudaGetSymbolAddress((void**)&pX3, g_X3);
        cudaFuncSetAttribute(tgemm_kernel<1>,
            cudaFuncAttributeMaxDynamicSharedMemorySize, SMEM_DYN);
        cudaFuncSetAttribute(tgemm_kernel<2>,
            cudaFuncAttributeMaxDynamicSharedMemorySize, SMEM_DYN);
        cudaFuncSetAttribute(tgemm_kernel<3>,
            cudaFuncAttributeMaxDynamicSharedMemorySize, SMEM_DYN);
        init_done = true;
    }

    dim3 blk(256);
    dim3 tblk(32, 8);

    // 1) scale = 1 / max(||W_read||, 1)
    norm_partial_kernel<<<256, 256>>>(W_read);
    norm_finish_kernel<<<1, 256>>>();

    // 2) W_comb = scale * W_read @ W_pre[512:768,:]   [fp32, proven kernel]
    gemm_wcomb_kernel<<<dim3(FF_D / 128, CENTER / 128), blk>>>(
        W_read, CTX_D, W_pre + (size_t)IN_D * FF_D, FF_D, CTX_D, pWcomb, FF_D);

    // 3) weight transpose + fp16 split
    wconv_kernel<<<dim3(FF_D / 32, IN_D / 32),   tblk>>>(W_pre,  FF_D, IN_D,
                                                         pB1h, pB1l, FF_D, 0);
    wconv_kernel<<<dim3(FF_D / 32, CENTER / 32), tblk>>>(pWcomb, FF_D, CENTER,
                                                         pB1h, pB1l, FF_D, IN_D);
    wconv_kernel<<<dim3(RNN_D / 32, FF_D / 32),  tblk>>>(Wx, RNN_D, FF_D,
                                                         pB2h, pB2l, FF_D + RNN_D, 0);
    wconv_kernel<<<dim3(RNN_D / 32, RNN_D / 32), tblk>>>(Wh, RNN_D, RNN_D,
                                                         pB2h, pB2l, FF_D + RNN_D, FF_D);
    wconv_kernel<<<dim3(TOT_D / 32, RNN_D / 32), tblk>>>(W_post, TOT_D, RNN_D,
                                                         pB3h, pB3l, RNN_D, 0);

    // 4) activation converts: inputs|center -> X1, state -> X2[:,1024:]
    {
        int t4 = BATCH * IN_D / 4;
        aconv_kernel<<<(t4 + 255) / 256, 256>>>(inputs, IN_D,
                                                pX1, FF_D, 0, t4);
        aconv_kernel<<<(t4 + 255) / 256, 256>>>(center, CENTER,
                                                pX1, FF_D, IN_D, t4);
        int t4s = BATCH * RNN_D / 4;
        aconv_kernel<<<(t4s + 255) / 256, 256>>>(state, RNN_D,
                                                 pX2, FF_D + RNN_D, FF_D, t4s);
    }

    // 5) rnn_in = relu(X1 @ B1^T + b_pre)  -> fp16 into X2[:, :1024]
    tgemm_kernel<1><<<dim3(FF_D / 128, BATCH / 128), blk, SMEM_DYN>>>(
        pX1, pB1h, pB1l, FF_D, b_pre,
        nullptr, 0, nullptr, pX2, FF_D + RNN_D);

    // 6) h_new = tanh(X2 @ B2^T + b_rnn)   -> fp32 out + fp16 X3
    tgemm_kernel<2><<<dim3(RNN_D / 128, BATCH / 128), blk, SMEM_DYN>>>(
        pX2, pB2h, pB2l, FF_D + RNN_D, b_rnn,
        h_new, RNN_D, nullptr, pX3, RNN_D);

    // 7) [net | toc] = relu(X3 @ B3^T + b_post)
    tgemm_kernel<3><<<dim3(TOT_D / 128, BATCH / 128), blk, SMEM_DYN>>>(
        pX3, pB3h, pB3l, RNN_D, b_post,
        net, OUT_D, toc, nullptr, 0);
}